// round 1
// baseline (speedup 1.0000x reference)
#include <cuda_runtime.h>
#include <math.h>

// Problem constants (fixed shapes)
#define Bd   2
#define Sd   2048
#define Dd   2048
#define Hd   16
#define HDd  128
#define NTOK 4096            // B*S
#define BH   32              // B*H

// Scratch (device globals; no dynamic allocation allowed)
__device__ float g_q[(long)BH * Sd * HDd];          // [B,H,S,HD]
__device__ float g_k[(long)BH * Sd * HDd];
__device__ float g_v[(long)BH * Sd * HDd];
__device__ float g_p[(long)BH * Sd * Sd];           // attention scores/probs
__device__ float g_ctx[(long)NTOK * Dd];            // [B,S,H*HD]

// ---------------------------------------------------------------------------
// SGEMM core: 128x128 tile, K-step 8, 256 threads, 8x8 per-thread.
// NT: C[m,n] = sum_k A[m,k] * B[n,k]   (A,B both K-contiguous)
// ---------------------------------------------------------------------------
__device__ __forceinline__ void core_nt(const float* __restrict__ A,
                                        const float* __restrict__ B,
                                        int K, int lda, int ldb,
                                        float acc[8][8]) {
    __shared__ float As[8][128];
    __shared__ float Bs[8][128];
    const int tid = threadIdx.x;
    const int row = tid >> 1;          // 0..127
    const int kv  = (tid & 1) * 4;     // 0 or 4
    const int tx  = tid & 15;
    const int ty  = tid >> 4;

    for (int k0 = 0; k0 < K; k0 += 8) {
        float4 av = *(const float4*)(A + (long)row * lda + k0 + kv);
        float4 bv = *(const float4*)(B + (long)row * ldb + k0 + kv);
        As[kv + 0][row] = av.x; As[kv + 1][row] = av.y;
        As[kv + 2][row] = av.z; As[kv + 3][row] = av.w;
        Bs[kv + 0][row] = bv.x; Bs[kv + 1][row] = bv.y;
        Bs[kv + 2][row] = bv.z; Bs[kv + 3][row] = bv.w;
        __syncthreads();
#pragma unroll
        for (int kk = 0; kk < 8; kk++) {
            float a[8], b[8];
#pragma unroll
            for (int i = 0; i < 8; i++) { a[i] = As[kk][ty * 8 + i]; b[i] = Bs[kk][tx * 8 + i]; }
#pragma unroll
            for (int i = 0; i < 8; i++)
#pragma unroll
                for (int j = 0; j < 8; j++)
                    acc[i][j] += a[i] * b[j];
        }
        __syncthreads();
    }
}

// NN: C[m,n] = sum_k A[m,k] * B[k,n]   (B is N-contiguous)
__device__ __forceinline__ void core_nn(const float* __restrict__ A,
                                        const float* __restrict__ B,
                                        int K, int lda, int ldb,
                                        float acc[8][8]) {
    __shared__ float As[8][128];
    __shared__ float Bs[8][128];
    const int tid  = threadIdx.x;
    const int row  = tid >> 1;         // A load: 0..127
    const int kv   = (tid & 1) * 4;
    const int krow = tid >> 5;         // B load: 0..7
    const int nv   = (tid & 31) * 4;   // 0..124
    const int tx   = tid & 15;
    const int ty   = tid >> 4;

    for (int k0 = 0; k0 < K; k0 += 8) {
        float4 av = *(const float4*)(A + (long)row * lda + k0 + kv);
        float4 bv = *(const float4*)(B + (long)(k0 + krow) * ldb + nv);
        As[kv + 0][row] = av.x; As[kv + 1][row] = av.y;
        As[kv + 2][row] = av.z; As[kv + 3][row] = av.w;
        *(float4*)&Bs[krow][nv] = bv;
        __syncthreads();
#pragma unroll
        for (int kk = 0; kk < 8; kk++) {
            float a[8], b[8];
#pragma unroll
            for (int i = 0; i < 8; i++) { a[i] = As[kk][ty * 8 + i]; b[i] = Bs[kk][tx * 8 + i]; }
#pragma unroll
            for (int i = 0; i < 8; i++)
#pragma unroll
                for (int j = 0; j < 8; j++)
                    acc[i][j] += a[i] * b[j];
        }
        __syncthreads();
    }
}

// ---------------------------------------------------------------------------
// 1) QKV projections: y = x @ W^T + b, written as [B,H,S,HD]. grid.z = {q,k,v}
// ---------------------------------------------------------------------------
__global__ void __launch_bounds__(256) k_proj(
    const float* __restrict__ hs,
    const float* __restrict__ Wq, const float* __restrict__ Wk, const float* __restrict__ Wv,
    const float* __restrict__ bq, const float* __restrict__ bk, const float* __restrict__ bv) {
    const int m0 = blockIdx.y * 128;
    const int n0 = blockIdx.x * 128;
    const int wz = blockIdx.z;
    const float* W    = (wz == 0) ? Wq : (wz == 1) ? Wk : Wv;
    const float* bias = (wz == 0) ? bq : (wz == 1) ? bk : bv;
    float*       out  = (wz == 0) ? g_q : (wz == 1) ? g_k : g_v;

    float acc[8][8] = {};
    core_nt(hs + (long)m0 * Dd, W + (long)n0 * Dd, Dd, Dd, Dd, acc);

    const int tx = threadIdx.x & 15, ty = threadIdx.x >> 4;
#pragma unroll
    for (int i = 0; i < 8; i++) {
        const int m = m0 + ty * 8 + i;
        const int b = m >> 11, s = m & 2047;
#pragma unroll
        for (int j = 0; j < 8; j++) {
            const int n = n0 + tx * 8 + j;
            const int h = n >> 7, hd = n & 127;
            out[(((long)(b * Hd + h) * Sd) + s) * HDd + hd] = acc[i][j] + bias[n];
        }
    }
}

// ---------------------------------------------------------------------------
// 2) RoPE (note intentional sin/cos swap to match reference):
//    out[j]    = x[j]*sin(th) - x[j+64]*cos(th)
//    out[j+64] = x[j+64]*sin(th) + x[j]*cos(th)
// ---------------------------------------------------------------------------
__global__ void __launch_bounds__(256) k_rope() {
    const long idx = (long)blockIdx.x * 256 + threadIdx.x;   // over BH*S*64
    const int  j   = (int)(idx & 63);
    const long r   = idx >> 6;
    const int  s   = (int)(r & 2047);
    const int  bh  = (int)(r >> 11);
    const float inv = 1.0f / powf(10000.0f, (float)j * (1.0f / 64.0f));
    const float th  = (float)s * inv;
    float sn, cs;
    sincosf(th, &sn, &cs);
    const long base = ((long)bh * Sd + s) * HDd + j;

    float lo = g_q[base], hi = g_q[base + 64];
    g_q[base]      = lo * sn - hi * cs;
    g_q[base + 64] = hi * sn + lo * cs;

    lo = g_k[base]; hi = g_k[base + 64];
    g_k[base]      = lo * sn - hi * cs;
    g_k[base + 64] = hi * sn + lo * cs;
}

// ---------------------------------------------------------------------------
// 3) scores = (Q @ K^T) / sqrt(HD), batched over bh
// ---------------------------------------------------------------------------
__global__ void __launch_bounds__(256) k_scores() {
    const int bz = blockIdx.z;
    const float* A = g_q + (long)bz * Sd * HDd + (long)blockIdx.y * 128 * HDd;
    const float* B = g_k + (long)bz * Sd * HDd + (long)blockIdx.x * 128 * HDd;
    float acc[8][8] = {};
    core_nt(A, B, HDd, HDd, HDd, acc);

    float* C = g_p + (long)bz * Sd * Sd + (long)(blockIdx.y * 128) * Sd + blockIdx.x * 128;
    const float sc = 0.08838834764831845f;  // 1/sqrt(128)
    const int tx = threadIdx.x & 15, ty = threadIdx.x >> 4;
#pragma unroll
    for (int i = 0; i < 8; i++)
#pragma unroll
        for (int j = 0; j < 8; j++)
            C[(long)(ty * 8 + i) * Sd + tx * 8 + j] = acc[i][j] * sc;
}

// ---------------------------------------------------------------------------
// 4) row softmax over scores (one block per row, 2048 elems)
// ---------------------------------------------------------------------------
__global__ void __launch_bounds__(256) k_softmax() {
    float* p = g_p + (long)blockIdx.x * Sd;
    const int tid = threadIdx.x;
    float v[8];
    float mx = -1e30f;
#pragma unroll
    for (int i = 0; i < 8; i++) { v[i] = p[i * 256 + tid]; mx = fmaxf(mx, v[i]); }

    __shared__ float red[256];
    red[tid] = mx;
    __syncthreads();
    for (int o = 128; o > 0; o >>= 1) {
        if (tid < o) red[tid] = fmaxf(red[tid], red[tid + o]);
        __syncthreads();
    }
    mx = red[0];
    __syncthreads();

    float sm = 0.0f;
#pragma unroll
    for (int i = 0; i < 8; i++) { v[i] = expf(v[i] - mx); sm += v[i]; }
    red[tid] = sm;
    __syncthreads();
    for (int o = 128; o > 0; o >>= 1) {
        if (tid < o) red[tid] += red[tid + o];
        __syncthreads();
    }
    const float inv = 1.0f / red[0];
#pragma unroll
    for (int i = 0; i < 8; i++) p[i * 256 + tid] = v[i] * inv;
}

// ---------------------------------------------------------------------------
// 5) ctx = P @ V, written as [B,S,H*HD] (so out-proj A is dense)
// ---------------------------------------------------------------------------
__global__ void __launch_bounds__(256) k_ctx() {
    const int bz = blockIdx.z;
    const float* A = g_p + (long)bz * Sd * Sd + (long)blockIdx.y * 128 * Sd;
    const float* B = g_v + (long)bz * Sd * HDd;
    float acc[8][8] = {};
    core_nn(A, B, Sd, Sd, HDd, acc);

    const int b = bz >> 4, h = bz & 15;
    float* C = g_ctx + (long)b * Sd * Dd + (long)h * HDd + (long)(blockIdx.y * 128) * Dd;
    const int tx = threadIdx.x & 15, ty = threadIdx.x >> 4;
#pragma unroll
    for (int i = 0; i < 8; i++)
#pragma unroll
        for (int j = 0; j < 8; j++)
            C[(long)(ty * 8 + i) * Dd + tx * 8 + j] = acc[i][j];
}

// ---------------------------------------------------------------------------
// 6) out = ctx @ Wo^T + bo
// ---------------------------------------------------------------------------
__global__ void __launch_bounds__(256) k_out(const float* __restrict__ Wo,
                                             const float* __restrict__ bo,
                                             float* __restrict__ out) {
    const int m0 = blockIdx.y * 128;
    const int n0 = blockIdx.x * 128;
    float acc[8][8] = {};
    core_nt(g_ctx + (long)m0 * Dd, Wo + (long)n0 * Dd, Dd, Dd, Dd, acc);

    const int tx = threadIdx.x & 15, ty = threadIdx.x >> 4;
#pragma unroll
    for (int i = 0; i < 8; i++) {
        const int m = m0 + ty * 8 + i;
#pragma unroll
        for (int j = 0; j < 8; j++) {
            const int n = n0 + tx * 8 + j;
            out[(long)m * Dd + n] = acc[i][j] + bo[n];
        }
    }
}

// ---------------------------------------------------------------------------
extern "C" void kernel_launch(void* const* d_in, const int* in_sizes, int n_in,
                              void* d_out, int out_size) {
    const float* hs = (const float*)d_in[0];
    const float* Wq = (const float*)d_in[1];
    const float* bq = (const float*)d_in[2];
    const float* Wk = (const float*)d_in[3];
    const float* bk = (const float*)d_in[4];
    const float* Wv = (const float*)d_in[5];
    const float* bv = (const float*)d_in[6];
    const float* Wo = (const float*)d_in[7];
    const float* bo = (const float*)d_in[8];
    float* out = (float*)d_out;

    // 1) QKV projections -> [B,H,S,HD]
    k_proj<<<dim3(Dd / 128, NTOK / 128, 3), 256>>>(hs, Wq, Wk, Wv, bq, bk, bv);
    // 2) RoPE in place on q,k
    k_rope<<<(BH * Sd * 64) / 256, 256>>>();
    // 3) scores = QK^T / sqrt(HD)
    k_scores<<<dim3(Sd / 128, Sd / 128, BH), 256>>>();
    // 4) softmax rows
    k_softmax<<<BH * Sd, 256>>>();
    // 5) ctx = P @ V -> [B,S,D]
    k_ctx<<<dim3(1, Sd / 128, BH), 256>>>();
    // 6) out = ctx @ Wo^T + bo
    k_out<<<dim3(Dd / 128, NTOK / 128, 1), 256>>>(Wo, bo, out);
}

// round 3
// speedup vs baseline: 5.7843x; 5.7843x over previous
#include <cuda_runtime.h>
#include <cuda_fp16.h>
#include <cstdint>
#include <math.h>

// Fixed shapes
#define Sd   2048
#define Dd   2048
#define Hd   16
#define HDd  128
#define NTOK 4096            // B*S
#define BH   32              // B*H

// ---------------------------------------------------------------------------
// Device scratch (static globals; no dynamic allocation allowed)
// ---------------------------------------------------------------------------
__device__ __align__(16) __half g_hs16[(long)NTOK * Dd];
__device__ __align__(16) __half g_w16[(long)4 * Dd * Dd];       // Wq,Wk,Wv,Wo
__device__ __align__(16) __half g_q16[(long)BH * Sd * HDd];     // [bh][s][hd]
__device__ __align__(16) __half g_k16[(long)BH * Sd * HDd];
__device__ __align__(16) __half g_vT16[(long)BH * HDd * Sd];    // [bh][hd][t]
__device__ __align__(16) __half g_pf16[(long)BH * Sd * Sd];     // probs fp16
__device__ __align__(16) __half g_ctx16[(long)NTOK * Dd];       // [b,s,D]
__device__ float g_p[(long)BH * Sd * Sd];                       // scores fp32

__device__ __forceinline__ uint32_t smem_to_u32(const void* p) {
    uint32_t a;
    asm("{ .reg .u64 t; cvta.to.shared.u64 t, %1; cvt.u32.u64 %0, t; }" : "=r"(a) : "l"(p));
    return a;
}

// ---------------------------------------------------------------------------
// fp32 -> fp16 convert, 8 elems/thread
// ---------------------------------------------------------------------------
__global__ void __launch_bounds__(256) k_tohalf(const float* __restrict__ s,
                                                __half* __restrict__ d) {
    const long i = ((long)blockIdx.x * 256 + threadIdx.x) * 8;
    float4 x = *(const float4*)(s + i);
    float4 y = *(const float4*)(s + i + 4);
    __half2 h0 = __floats2half2_rn(x.x, x.y);
    __half2 h1 = __floats2half2_rn(x.z, x.w);
    __half2 h2 = __floats2half2_rn(y.x, y.y);
    __half2 h3 = __floats2half2_rn(y.z, y.w);
    uint4 o;
    o.x = *(uint32_t*)&h0; o.y = *(uint32_t*)&h1;
    o.z = *(uint32_t*)&h2; o.w = *(uint32_t*)&h3;
    *(uint4*)(d + i) = o;
}

// ---------------------------------------------------------------------------
// Unified HMMA GEMM (mma.sync m16n8k16 fp16->fp32).
// Tile 128x128, K-chunk 64, 4-stage cp.async pipeline, 8 warps (2x4),
// warp tile 64x32. All GEMMs are NT (both operands K-contiguous).
//
// mode 0: QKV proj (bz selects q/k/v). +bias; q/k: fused RoPE -> g_q16/g_k16
//         [bh][s][hd]; v: transposed store -> g_vT16 [bh][hd][t].
// mode 3: scores = (q k^T)/sqrt(128) -> g_p fp32. K=128, bz=bh.
// mode 4: ctx = P V  (A=g_pf16, B=g_vT16) -> g_ctx16 [b,s,D]. bz=bh.
// mode 5: out = ctx Wo^T + bo -> fp32 outp.
// ---------------------------------------------------------------------------
#define STAGES 4
#define CHUNK 64
#define STAGE_BYTES 32768                 // A 128x64 + B 128x64 halves
#define GEMM_SMEM (STAGES * STAGE_BYTES)  // 131072

__global__ void __launch_bounds__(256) k_hgemm(
    const float* __restrict__ bias_q, const float* __restrict__ bias_k,
    const float* __restrict__ bias_v, float* __restrict__ outp, int mode) {
    extern __shared__ char smem[];
    const uint32_t sb = smem_to_u32(smem);
    const int tid = threadIdx.x, lane = tid & 31, wid = tid >> 5;
    const int wm = wid >> 2, wn = wid & 3;
    const int m0 = blockIdx.y * 128, n0 = blockIdx.x * 128, bz = blockIdx.z;

    const __half *Ap, *Bp;
    const float* bias = nullptr;
    int lda, ldb, K;
    if (mode == 0) {
        Ap = g_hs16 + (long)m0 * Dd; lda = Dd;
        Bp = g_w16 + (long)bz * Dd * Dd + (long)n0 * Dd; ldb = Dd; K = Dd;
        bias = (bz == 0) ? bias_q : (bz == 1) ? bias_k : bias_v;
    } else if (mode == 3) {
        Ap = g_q16 + (long)bz * Sd * HDd + (long)m0 * HDd; lda = HDd;
        Bp = g_k16 + (long)bz * Sd * HDd + (long)n0 * HDd; ldb = HDd; K = HDd;
    } else if (mode == 4) {
        Ap = g_pf16 + (long)bz * Sd * Sd + (long)m0 * Sd; lda = Sd;
        Bp = g_vT16 + (long)bz * HDd * Sd + (long)n0 * Sd; ldb = Sd; K = Sd;
    } else {
        Ap = g_ctx16 + (long)m0 * Dd; lda = Dd;
        Bp = g_w16 + (long)3 * Dd * Dd + (long)n0 * Dd; ldb = Dd; K = Dd;
        bias = bias_q;  // bo passed via first bias arg
    }
    const int C = K / CHUNK;

    __shared__ float bias_s[128];
    if (tid < 128) bias_s[tid] = bias ? bias[n0 + tid] : 0.0f;

    // stage loader: per thread 4 x 16B for A, 4 x 16B for B
    auto load_stage = [&](int st, int k0) {
        const uint32_t base = sb + (uint32_t)st * STAGE_BYTES;
#pragma unroll
        for (int i = 0; i < 4; i++) {
            const int id = tid + i * 256;
            const int row = id >> 3, ch = id & 7;
            uint32_t off = (uint32_t)(row * 128 + ch * 16);
            uint32_t dst = base + (off ^ ((off >> 3) & 0x70));
            const __half* g = Ap + (long)row * lda + k0 + ch * 8;
            asm volatile("cp.async.cg.shared.global [%0], [%1], 16;" :: "r"(dst), "l"(g));
        }
#pragma unroll
        for (int i = 0; i < 4; i++) {
            const int id = tid + i * 256;
            const int row = id >> 3, ch = id & 7;
            uint32_t off = (uint32_t)(row * 128 + ch * 16);
            uint32_t dst = base + 16384 + (off ^ ((off >> 3) & 0x70));
            const __half* g = Bp + (long)row * ldb + k0 + ch * 8;
            asm volatile("cp.async.cg.shared.global [%0], [%1], 16;" :: "r"(dst), "l"(g));
        }
    };

    float c[4][4][4] = {};

    auto compute = [&](int st) {
        const uint32_t abase = sb + (uint32_t)st * STAGE_BYTES;
        const uint32_t bbase = abase + 16384;
#pragma unroll
        for (int kk = 0; kk < 4; kk++) {
            uint32_t a[4][4], b[4][2];
#pragma unroll
            for (int mi = 0; mi < 4; mi++) {
                const int row = wm * 64 + mi * 16 + (lane & 15);
                uint32_t off = (uint32_t)(row * 128 + kk * 32 + ((lane >> 4) << 4));
                uint32_t ad = abase + (off ^ ((off >> 3) & 0x70));
                asm volatile("ldmatrix.sync.aligned.m8n8.x4.shared.b16 {%0,%1,%2,%3}, [%4];"
                             : "=r"(a[mi][0]), "=r"(a[mi][1]), "=r"(a[mi][2]), "=r"(a[mi][3])
                             : "r"(ad));
            }
#pragma unroll
            for (int ni = 0; ni < 4; ni++) {
                const int row = wn * 32 + ni * 8 + (lane & 7);
                uint32_t off = (uint32_t)(row * 128 + kk * 32 + (((lane >> 3) & 1) << 4));
                uint32_t bd = bbase + (off ^ ((off >> 3) & 0x70));
                asm volatile("ldmatrix.sync.aligned.m8n8.x2.shared.b16 {%0,%1}, [%2];"
                             : "=r"(b[ni][0]), "=r"(b[ni][1]) : "r"(bd));
            }
#pragma unroll
            for (int mi = 0; mi < 4; mi++)
#pragma unroll
                for (int ni = 0; ni < 4; ni++)
                    asm volatile(
                        "mma.sync.aligned.m16n8k16.row.col.f32.f16.f16.f32 "
                        "{%0,%1,%2,%3}, {%4,%5,%6,%7}, {%8,%9}, {%0,%1,%2,%3};"
                        : "+f"(c[mi][ni][0]), "+f"(c[mi][ni][1]),
                          "+f"(c[mi][ni][2]), "+f"(c[mi][ni][3])
                        : "r"(a[mi][0]), "r"(a[mi][1]), "r"(a[mi][2]), "r"(a[mi][3]),
                          "r"(b[ni][0]), "r"(b[ni][1]));
        }
    };

    // pipeline
    for (int s = 0; s < STAGES - 1 && s < C; s++) {
        load_stage(s, s * CHUNK);
        asm volatile("cp.async.commit_group;" ::: "memory");
    }
    for (int c0 = 0; c0 < C; c0++) {
        if (c0 + STAGES - 1 < C) load_stage((c0 + STAGES - 1) % STAGES, (c0 + STAGES - 1) * CHUNK);
        asm volatile("cp.async.commit_group;" ::: "memory");
        asm volatile("cp.async.wait_group 2;" ::: "memory");
        __syncthreads();
        compute(c0 % STAGES);
        __syncthreads();
    }
    asm volatile("cp.async.wait_all;" ::: "memory");
    __syncthreads();

    // ---- epilogue: accum (+bias) -> padded fp32 smem tile ----
    float* sm = (float*)smem;  // [128][129]
#pragma unroll
    for (int mi = 0; mi < 4; mi++)
#pragma unroll
        for (int ni = 0; ni < 4; ni++) {
            const int r0 = wm * 64 + mi * 16 + (lane >> 2);
            const int cc = wn * 32 + ni * 8 + (lane & 3) * 2;
            sm[r0 * 129 + cc]           = c[mi][ni][0] + bias_s[cc];
            sm[r0 * 129 + cc + 1]       = c[mi][ni][1] + bias_s[cc + 1];
            sm[(r0 + 8) * 129 + cc]     = c[mi][ni][2] + bias_s[cc];
            sm[(r0 + 8) * 129 + cc + 1] = c[mi][ni][3] + bias_s[cc + 1];
        }
    __syncthreads();

    if (mode == 0) {
        const int b = m0 >> 11, h = n0 >> 7;
        if (bz < 2) {  // q or k: RoPE then [bh][s][hd]
            __half* out = (bz == 0) ? g_q16 : g_k16;
            const long obase = ((long)(b * Hd + h) * Sd + (m0 & 2047)) * HDd;
            for (int idx = tid; idx < 128 * 64; idx += 256) {
                const int r = idx >> 6, j = idx & 63;
                const float inv = 1.0f / powf(10000.0f, (float)j * (1.0f / 64.0f));
                const int s = (m0 & 2047) + r;
                float sn, cs;
                sincosf((float)s * inv, &sn, &cs);
                const float lo = sm[r * 129 + j], hi = sm[r * 129 + j + 64];
                out[obase + (long)r * HDd + j]      = __float2half(lo * sn - hi * cs);
                out[obase + (long)r * HDd + j + 64] = __float2half(hi * sn + lo * cs);
            }
        } else {  // v: transposed [bh][hd][t]
            const long obase = (long)(b * Hd + h) * HDd * Sd;
            const int t0 = m0 & 2047;
            for (int idx = tid; idx < 128 * 128; idx += 256) {
                const int hd = idx >> 7, t = idx & 127;
                g_vT16[obase + (long)hd * Sd + t0 + t] = __float2half(sm[t * 129 + hd]);
            }
        }
    } else if (mode == 3) {
        float* out = g_p + (long)bz * Sd * Sd + (long)m0 * Sd + n0;
        for (int idx = tid; idx < 128 * 128; idx += 256) {
            const int r = idx >> 7, cc2 = idx & 127;
            out[(long)r * Sd + cc2] = sm[r * 129 + cc2] * 0.08838834764831845f;
        }
    } else if (mode == 4) {
        const int b = bz >> 4, h = bz & 15;
        const long obase = (long)b * Sd * Dd + (long)m0 * Dd + h * HDd;
        for (int idx = tid; idx < 128 * 128; idx += 256) {
            const int r = idx >> 7, cc2 = idx & 127;
            g_ctx16[obase + (long)r * Dd + cc2] = __float2half(sm[r * 129 + cc2]);
        }
    } else {
        for (int idx = tid; idx < 128 * 128; idx += 256) {
            const int r = idx >> 7, cc2 = idx & 127;
            outp[(long)(m0 + r) * Dd + n0 + cc2] = sm[r * 129 + cc2];
        }
    }
}

// ---------------------------------------------------------------------------
// Row softmax: fp32 scores -> fp16 probs
// ---------------------------------------------------------------------------
__global__ void __launch_bounds__(256) k_softmax() {
    const float* p = g_p + (long)blockIdx.x * Sd;
    __half* o = g_pf16 + (long)blockIdx.x * Sd;
    const int tid = threadIdx.x;
    float v[8];
    float mx = -1e30f;
#pragma unroll
    for (int i = 0; i < 8; i++) { v[i] = p[i * 256 + tid]; mx = fmaxf(mx, v[i]); }
    __shared__ float red[256];
    red[tid] = mx;
    __syncthreads();
    for (int ofs = 128; ofs > 0; ofs >>= 1) {
        if (tid < ofs) red[tid] = fmaxf(red[tid], red[tid + ofs]);
        __syncthreads();
    }
    mx = red[0];
    __syncthreads();
    float smv = 0.0f;
#pragma unroll
    for (int i = 0; i < 8; i++) { v[i] = expf(v[i] - mx); smv += v[i]; }
    red[tid] = smv;
    __syncthreads();
    for (int ofs = 128; ofs > 0; ofs >>= 1) {
        if (tid < ofs) red[tid] += red[tid + ofs];
        __syncthreads();
    }
    const float inv = 1.0f / red[0];
#pragma unroll
    for (int i = 0; i < 8; i++) o[i * 256 + tid] = __float2half(v[i] * inv);
}

// ---------------------------------------------------------------------------
extern "C" void kernel_launch(void* const* d_in, const int* in_sizes, int n_in,
                              void* d_out, int out_size) {
    const float* hs = (const float*)d_in[0];
    const float* Wq = (const float*)d_in[1];
    const float* bq = (const float*)d_in[2];
    const float* Wk = (const float*)d_in[3];
    const float* bk = (const float*)d_in[4];
    const float* Wv = (const float*)d_in[5];
    const float* bv = (const float*)d_in[6];
    const float* Wo = (const float*)d_in[7];
    const float* bo = (const float*)d_in[8];
    float* out = (float*)d_out;

    static bool attr_set = false;
    if (!attr_set) {
        cudaFuncSetAttribute(k_hgemm, cudaFuncAttributeMaxDynamicSharedMemorySize, GEMM_SMEM);
        attr_set = true;
    }

    __half* w16;
    cudaGetSymbolAddress((void**)&w16, g_w16);
    __half* hs16;
    cudaGetSymbolAddress((void**)&hs16, g_hs16);

    // fp32 -> fp16 conversions
    k_tohalf<<<(NTOK * (long)Dd) / 2048, 256>>>(hs, hs16);
    k_tohalf<<<((long)Dd * Dd) / 2048, 256>>>(Wq, w16);
    k_tohalf<<<((long)Dd * Dd) / 2048, 256>>>(Wk, w16 + (long)Dd * Dd);
    k_tohalf<<<((long)Dd * Dd) / 2048, 256>>>(Wv, w16 + (long)2 * Dd * Dd);
    k_tohalf<<<((long)Dd * Dd) / 2048, 256>>>(Wo, w16 + (long)3 * Dd * Dd);

    // QKV projections (+bias, +RoPE for q/k, transpose for v)
    k_hgemm<<<dim3(Dd / 128, NTOK / 128, 3), 256, GEMM_SMEM>>>(bq, bk, bv, nullptr, 0);
    // scores = q k^T / sqrt(hd)
    k_hgemm<<<dim3(Sd / 128, Sd / 128, BH), 256, GEMM_SMEM>>>(nullptr, nullptr, nullptr, nullptr, 3);
    // softmax -> fp16 probs
    k_softmax<<<BH * Sd, 256>>>();
    // ctx = P V
    k_hgemm<<<dim3(1, Sd / 128, BH), 256, GEMM_SMEM>>>(nullptr, nullptr, nullptr, nullptr, 4);
    // out = ctx Wo^T + bo
    k_hgemm<<<dim3(Dd / 128, NTOK / 128, 1), 256, GEMM_SMEM>>>(bo, nullptr, nullptr, out, 5);
}

// round 4
// speedup vs baseline: 8.3785x; 1.4485x over previous
#include <cuda_runtime.h>
#include <cuda_fp16.h>
#include <cstdint>
#include <math.h>

// Fixed shapes
#define Sd   2048
#define Dd   2048
#define Hd   16
#define HDd  128
#define NTOK 4096            // B*S
#define BH   32              // B*H

// ---------------------------------------------------------------------------
// Device scratch
// ---------------------------------------------------------------------------
__device__ __align__(16) __half g_hs16[(long)NTOK * Dd];
__device__ __align__(16) __half g_w16[(long)4 * Dd * Dd];       // Wq,Wk,Wv,Wo
__device__ __align__(16) __half g_q16[(long)BH * Sd * HDd];     // [bh][s][hd]
__device__ __align__(16) __half g_k16[(long)BH * Sd * HDd];     // [bh][t][hd]
__device__ __align__(16) __half g_vT16[(long)BH * HDd * Sd];    // [bh][hd][t]
__device__ __align__(16) __half g_ctx16[(long)NTOK * Dd];       // [b,s,D]

__device__ __forceinline__ uint32_t smem_to_u32(const void* p) {
    uint32_t a;
    asm("{ .reg .u64 t; cvta.to.shared.u64 t, %1; cvt.u32.u64 %0, t; }" : "=r"(a) : "l"(p));
    return a;
}

// ---------------------------------------------------------------------------
// fp32 -> fp16 convert, 8 elems/thread
// ---------------------------------------------------------------------------
__global__ void __launch_bounds__(256) k_tohalf(const float* __restrict__ s,
                                                __half* __restrict__ d) {
    const long i = ((long)blockIdx.x * 256 + threadIdx.x) * 8;
    float4 x = *(const float4*)(s + i);
    float4 y = *(const float4*)(s + i + 4);
    __half2 h0 = __floats2half2_rn(x.x, x.y);
    __half2 h1 = __floats2half2_rn(x.z, x.w);
    __half2 h2 = __floats2half2_rn(y.x, y.y);
    __half2 h3 = __floats2half2_rn(y.z, y.w);
    uint4 o;
    o.x = *(uint32_t*)&h0; o.y = *(uint32_t*)&h1;
    o.z = *(uint32_t*)&h2; o.w = *(uint32_t*)&h3;
    *(uint4*)(d + i) = o;
}

// ---------------------------------------------------------------------------
// HMMA GEMM for projections. Tile 128x128, K-chunk 64, 4-stage cp.async,
// 8 warps (2x4), warp tile 64x32. NT layout.
// mode 0: QKV proj (bz selects). +bias; q/k: RoPE -> g_q16/g_k16; v -> g_vT16.
// mode 5: out = ctx Wo^T + bo -> fp32 outp.
// ---------------------------------------------------------------------------
#define STAGES 4
#define CHUNK 64
#define STAGE_BYTES 32768
#define GEMM_SMEM (STAGES * STAGE_BYTES)

__global__ void __launch_bounds__(256) k_hgemm(
    const float* __restrict__ bias_q, const float* __restrict__ bias_k,
    const float* __restrict__ bias_v, float* __restrict__ outp, int mode) {
    extern __shared__ char smem[];
    const uint32_t sb = smem_to_u32(smem);
    const int tid = threadIdx.x, lane = tid & 31, wid = tid >> 5;
    const int wm = wid >> 2, wn = wid & 3;
    const int m0 = blockIdx.y * 128, n0 = blockIdx.x * 128, bz = blockIdx.z;

    const __half *Ap, *Bp;
    const float* bias;
    if (mode == 0) {
        Ap = g_hs16 + (long)m0 * Dd;
        Bp = g_w16 + (long)bz * Dd * Dd + (long)n0 * Dd;
        bias = (bz == 0) ? bias_q : (bz == 1) ? bias_k : bias_v;
    } else {
        Ap = g_ctx16 + (long)m0 * Dd;
        Bp = g_w16 + (long)3 * Dd * Dd + (long)n0 * Dd;
        bias = bias_q;  // bo
    }
    const int K = Dd, C = K / CHUNK;

    __shared__ float bias_s[128];
    if (tid < 128) bias_s[tid] = bias[n0 + tid];

    auto load_stage = [&](int st, int k0) {
        const uint32_t base = sb + (uint32_t)st * STAGE_BYTES;
#pragma unroll
        for (int i = 0; i < 4; i++) {
            const int id = tid + i * 256;
            const int row = id >> 3, ch = id & 7;
            uint32_t off = (uint32_t)(row * 128 + ch * 16);
            uint32_t dst = base + (off ^ ((off >> 3) & 0x70));
            const __half* g = Ap + (long)row * Dd + k0 + ch * 8;
            asm volatile("cp.async.cg.shared.global [%0], [%1], 16;" :: "r"(dst), "l"(g));
        }
#pragma unroll
        for (int i = 0; i < 4; i++) {
            const int id = tid + i * 256;
            const int row = id >> 3, ch = id & 7;
            uint32_t off = (uint32_t)(row * 128 + ch * 16);
            uint32_t dst = base + 16384 + (off ^ ((off >> 3) & 0x70));
            const __half* g = Bp + (long)row * Dd + k0 + ch * 8;
            asm volatile("cp.async.cg.shared.global [%0], [%1], 16;" :: "r"(dst), "l"(g));
        }
    };

    float c[4][4][4] = {};

    auto compute = [&](int st) {
        const uint32_t abase = sb + (uint32_t)st * STAGE_BYTES;
        const uint32_t bbase = abase + 16384;
#pragma unroll
        for (int kk = 0; kk < 4; kk++) {
            uint32_t a[4][4], b[4][2];
#pragma unroll
            for (int mi = 0; mi < 4; mi++) {
                const int row = wm * 64 + mi * 16 + (lane & 15);
                uint32_t off = (uint32_t)(row * 128 + kk * 32 + ((lane >> 4) << 4));
                uint32_t ad = abase + (off ^ ((off >> 3) & 0x70));
                asm volatile("ldmatrix.sync.aligned.m8n8.x4.shared.b16 {%0,%1,%2,%3}, [%4];"
                             : "=r"(a[mi][0]), "=r"(a[mi][1]), "=r"(a[mi][2]), "=r"(a[mi][3])
                             : "r"(ad));
            }
#pragma unroll
            for (int ni = 0; ni < 4; ni++) {
                const int row = wn * 32 + ni * 8 + (lane & 7);
                uint32_t off = (uint32_t)(row * 128 + kk * 32 + (((lane >> 3) & 1) << 4));
                uint32_t bd = bbase + (off ^ ((off >> 3) & 0x70));
                asm volatile("ldmatrix.sync.aligned.m8n8.x2.shared.b16 {%0,%1}, [%2];"
                             : "=r"(b[ni][0]), "=r"(b[ni][1]) : "r"(bd));
            }
#pragma unroll
            for (int mi = 0; mi < 4; mi++)
#pragma unroll
                for (int ni = 0; ni < 4; ni++)
                    asm volatile(
                        "mma.sync.aligned.m16n8k16.row.col.f32.f16.f16.f32 "
                        "{%0,%1,%2,%3}, {%4,%5,%6,%7}, {%8,%9}, {%0,%1,%2,%3};"
                        : "+f"(c[mi][ni][0]), "+f"(c[mi][ni][1]),
                          "+f"(c[mi][ni][2]), "+f"(c[mi][ni][3])
                        : "r"(a[mi][0]), "r"(a[mi][1]), "r"(a[mi][2]), "r"(a[mi][3]),
                          "r"(b[ni][0]), "r"(b[ni][1]));
        }
    };

    for (int s = 0; s < STAGES - 1; s++) {
        load_stage(s, s * CHUNK);
        asm volatile("cp.async.commit_group;" ::: "memory");
    }
    for (int c0 = 0; c0 < C; c0++) {
        if (c0 + STAGES - 1 < C) load_stage((c0 + STAGES - 1) % STAGES, (c0 + STAGES - 1) * CHUNK);
        asm volatile("cp.async.commit_group;" ::: "memory");
        asm volatile("cp.async.wait_group 2;" ::: "memory");
        __syncthreads();
        compute(c0 % STAGES);
        __syncthreads();
    }
    asm volatile("cp.async.wait_all;" ::: "memory");
    __syncthreads();

    float* sm = (float*)smem;  // [128][129]
#pragma unroll
    for (int mi = 0; mi < 4; mi++)
#pragma unroll
        for (int ni = 0; ni < 4; ni++) {
            const int r0 = wm * 64 + mi * 16 + (lane >> 2);
            const int cc = wn * 32 + ni * 8 + (lane & 3) * 2;
            sm[r0 * 129 + cc]           = c[mi][ni][0] + bias_s[cc];
            sm[r0 * 129 + cc + 1]       = c[mi][ni][1] + bias_s[cc + 1];
            sm[(r0 + 8) * 129 + cc]     = c[mi][ni][2] + bias_s[cc];
            sm[(r0 + 8) * 129 + cc + 1] = c[mi][ni][3] + bias_s[cc + 1];
        }
    __syncthreads();

    if (mode == 0) {
        const int b = m0 >> 11, h = n0 >> 7;
        if (bz < 2) {  // q/k: RoPE -> [bh][s][hd]
            __half* out = (bz == 0) ? g_q16 : g_k16;
            const long obase = ((long)(b * Hd + h) * Sd + (m0 & 2047)) * HDd;
            for (int idx = tid; idx < 128 * 64; idx += 256) {
                const int r = idx >> 6, j = idx & 63;
                const float inv = 1.0f / powf(10000.0f, (float)j * (1.0f / 64.0f));
                const int s = (m0 & 2047) + r;
                float sn, cs;
                sincosf((float)s * inv, &sn, &cs);
                const float lo = sm[r * 129 + j], hi = sm[r * 129 + j + 64];
                out[obase + (long)r * HDd + j]      = __float2half(lo * sn - hi * cs);
                out[obase + (long)r * HDd + j + 64] = __float2half(hi * sn + lo * cs);
            }
        } else {  // v -> transposed [bh][hd][t]
            const long obase = (long)(b * Hd + h) * HDd * Sd;
            const int t0 = m0 & 2047;
            for (int idx = tid; idx < 128 * 128; idx += 256) {
                const int hd = idx >> 7, t = idx & 127;
                g_vT16[obase + (long)hd * Sd + t0 + t] = __float2half(sm[t * 129 + hd]);
            }
        }
    } else {
        for (int idx = tid; idx < 128 * 128; idx += 256) {
            const int r = idx >> 7, cc2 = idx & 127;
            outp[(long)(m0 + r) * Dd + n0 + cc2] = sm[r * 129 + cc2];
        }
    }
}

// ---------------------------------------------------------------------------
// Fused flash attention: per CTA = (q-tile of 128 rows, one bh).
// Loop over 16 k-tiles of 128: S = Q K^T, online softmax, O += P V.
// Q in registers; K tile [t][hd] and V^T tile [hd][t] in smem (pitch 272B,
// conflict-free ldmatrix without swizzle). Double-buffered cp.async.
// Output: ctx fp16 -> g_ctx16 [b,s,D].
// ---------------------------------------------------------------------------
#define PITCH 272
#define TILEB (128 * PITCH)          // 34816
#define FA_SMEM (4 * TILEB)          // 139264

__global__ void __launch_bounds__(256, 1) k_fattn() {
    extern __shared__ char smem[];
    const uint32_t sb = smem_to_u32(smem);
    const int tid = threadIdx.x, lane = tid & 31, w = tid >> 5;
    const int m0 = blockIdx.x * 128, bh = blockIdx.y;

    const __half* Qp = g_q16 + (long)bh * Sd * HDd + (long)m0 * HDd;
    const __half* Kp = g_k16 + (long)bh * Sd * HDd;
    const __half* Vp = g_vT16 + (long)bh * HDd * Sd;

    auto kbase = [&](int i) { return sb + (uint32_t)i * TILEB; };
    auto vbase = [&](int i) { return sb + (uint32_t)(2 + i) * TILEB; };

    // load a 128x128 fp16 tile (row stride ldg halves) into pitched smem
    auto ldtile = [&](uint32_t base, const __half* g, int ldg) {
#pragma unroll
        for (int it = 0; it < 8; it++) {
            const int id = tid + it * 256;
            const int row = id >> 4, ch = id & 15;
            uint32_t dst = base + (uint32_t)(row * PITCH + ch * 16);
            const __half* src = g + (long)row * ldg + ch * 8;
            asm volatile("cp.async.cg.shared.global [%0], [%1], 16;" :: "r"(dst), "l"(src));
        }
    };

    // ---- prolog: Q tile -> smem -> registers ----
    ldtile(kbase(0), Qp, HDd);
    asm volatile("cp.async.commit_group;" ::: "memory");
    asm volatile("cp.async.wait_group 0;" ::: "memory");
    __syncthreads();

    uint32_t aq[8][4];
#pragma unroll
    for (int kk = 0; kk < 8; kk++) {
        const int row = w * 16 + (lane & 15);
        uint32_t ad = kbase(0) + (uint32_t)(row * PITCH + kk * 32 + ((lane >> 4) << 4));
        asm volatile("ldmatrix.sync.aligned.m8n8.x4.shared.b16 {%0,%1,%2,%3}, [%4];"
                     : "=r"(aq[kk][0]), "=r"(aq[kk][1]), "=r"(aq[kk][2]), "=r"(aq[kk][3])
                     : "r"(ad));
    }
    __syncthreads();

    float o[16][4] = {};
    float mr0 = -1e30f, mr1 = -1e30f, lr0 = 0.0f, lr1 = 0.0f;
    const float sc = 0.08838834764831845f;  // 1/sqrt(128)

    // prefetch k-tile 0
    ldtile(kbase(0), Kp, HDd);
    ldtile(vbase(0), Vp, Sd);
    asm volatile("cp.async.commit_group;" ::: "memory");

    for (int kt = 0; kt < 16; kt++) {
        const int buf = kt & 1;
        if (kt < 15) {
            ldtile(kbase(buf ^ 1), Kp + (long)(kt + 1) * 128 * HDd, HDd);
            ldtile(vbase(buf ^ 1), Vp + (kt + 1) * 128, Sd);
            asm volatile("cp.async.commit_group;" ::: "memory");
            asm volatile("cp.async.wait_group 1;" ::: "memory");
        } else {
            asm volatile("cp.async.wait_group 0;" ::: "memory");
        }
        __syncthreads();

        // ---- S = Q K^T (warp: 16 rows x 128 cols) ----
        float cS[16][4] = {};
#pragma unroll
        for (int kk = 0; kk < 8; kk++) {
#pragma unroll
            for (int ni = 0; ni < 16; ni++) {
                const int row = ni * 8 + (lane & 7);
                uint32_t bd = kbase(buf) + (uint32_t)(row * PITCH + kk * 32 + (((lane >> 3) & 1) << 4));
                uint32_t b0, b1;
                asm volatile("ldmatrix.sync.aligned.m8n8.x2.shared.b16 {%0,%1}, [%2];"
                             : "=r"(b0), "=r"(b1) : "r"(bd));
                asm volatile(
                    "mma.sync.aligned.m16n8k16.row.col.f32.f16.f16.f32 "
                    "{%0,%1,%2,%3}, {%4,%5,%6,%7}, {%8,%9}, {%0,%1,%2,%3};"
                    : "+f"(cS[ni][0]), "+f"(cS[ni][1]), "+f"(cS[ni][2]), "+f"(cS[ni][3])
                    : "r"(aq[kk][0]), "r"(aq[kk][1]), "r"(aq[kk][2]), "r"(aq[kk][3]),
                      "r"(b0), "r"(b1));
            }
        }

        // ---- online softmax (rows r0 = w*16+lane/4, r1 = r0+8) ----
        float mx0 = -1e30f, mx1 = -1e30f;
#pragma unroll
        for (int ni = 0; ni < 16; ni++) {
            mx0 = fmaxf(mx0, fmaxf(cS[ni][0], cS[ni][1]));
            mx1 = fmaxf(mx1, fmaxf(cS[ni][2], cS[ni][3]));
        }
        mx0 = fmaxf(mx0, __shfl_xor_sync(0xffffffffu, mx0, 1));
        mx0 = fmaxf(mx0, __shfl_xor_sync(0xffffffffu, mx0, 2));
        mx1 = fmaxf(mx1, __shfl_xor_sync(0xffffffffu, mx1, 1));
        mx1 = fmaxf(mx1, __shfl_xor_sync(0xffffffffu, mx1, 2));

        const float mn0 = fmaxf(mr0, mx0), mn1 = fmaxf(mr1, mx1);
        const float al0 = __expf((mr0 - mn0) * sc), al1 = __expf((mr1 - mn1) * sc);
        mr0 = mn0; mr1 = mn1;

        uint32_t pr0[16], pr1[16];
        float s0 = 0.0f, s1 = 0.0f;
#pragma unroll
        for (int ni = 0; ni < 16; ni++) {
            const float p0 = __expf((cS[ni][0] - mn0) * sc);
            const float p1 = __expf((cS[ni][1] - mn0) * sc);
            const float p2 = __expf((cS[ni][2] - mn1) * sc);
            const float p3 = __expf((cS[ni][3] - mn1) * sc);
            s0 += p0 + p1; s1 += p2 + p3;
            __half2 h0 = __floats2half2_rn(p0, p1);
            __half2 h1 = __floats2half2_rn(p2, p3);
            pr0[ni] = *(uint32_t*)&h0;
            pr1[ni] = *(uint32_t*)&h1;
        }
        s0 += __shfl_xor_sync(0xffffffffu, s0, 1);
        s0 += __shfl_xor_sync(0xffffffffu, s0, 2);
        s1 += __shfl_xor_sync(0xffffffffu, s1, 1);
        s1 += __shfl_xor_sync(0xffffffffu, s1, 2);
        lr0 = lr0 * al0 + s0;
        lr1 = lr1 * al1 + s1;

#pragma unroll
        for (int ni = 0; ni < 16; ni++) {
            o[ni][0] *= al0; o[ni][1] *= al0;
            o[ni][2] *= al1; o[ni][3] *= al1;
        }

        // ---- O += P V  (A = P frags, B = V^T tile) ----
#pragma unroll
        for (int kf = 0; kf < 8; kf++) {
            const uint32_t a0 = pr0[2 * kf], a1 = pr1[2 * kf];
            const uint32_t a2 = pr0[2 * kf + 1], a3 = pr1[2 * kf + 1];
#pragma unroll
            for (int ni = 0; ni < 16; ni++) {
                const int row = ni * 8 + (lane & 7);
                uint32_t bd = vbase(buf) + (uint32_t)(row * PITCH + kf * 32 + (((lane >> 3) & 1) << 4));
                uint32_t b0, b1;
                asm volatile("ldmatrix.sync.aligned.m8n8.x2.shared.b16 {%0,%1}, [%2];"
                             : "=r"(b0), "=r"(b1) : "r"(bd));
                asm volatile(
                    "mma.sync.aligned.m16n8k16.row.col.f32.f16.f16.f32 "
                    "{%0,%1,%2,%3}, {%4,%5,%6,%7}, {%8,%9}, {%0,%1,%2,%3};"
                    : "+f"(o[ni][0]), "+f"(o[ni][1]), "+f"(o[ni][2]), "+f"(o[ni][3])
                    : "r"(a0), "r"(a1), "r"(a2), "r"(a3), "r"(b0), "r"(b1));
            }
        }
        __syncthreads();
    }

    // ---- epilogue: O / l -> g_ctx16 [b, s, h*128 + hd] ----
    const int b = bh >> 4, h = bh & 15;
    const float i0 = 1.0f / lr0, i1 = 1.0f / lr1;
    const int r0 = m0 + w * 16 + (lane >> 2);
    const long base0 = (long)b * Sd * Dd + (long)r0 * Dd + h * HDd + (lane & 3) * 2;
    const long base1 = base0 + 8 * Dd;
#pragma unroll
    for (int ni = 0; ni < 16; ni++) {
        __half2 h0 = __floats2half2_rn(o[ni][0] * i0, o[ni][1] * i0);
        __half2 h1 = __floats2half2_rn(o[ni][2] * i1, o[ni][3] * i1);
        *(__half2*)(g_ctx16 + base0 + ni * 8) = h0;
        *(__half2*)(g_ctx16 + base1 + ni * 8) = h1;
    }
}

// ---------------------------------------------------------------------------
extern "C" void kernel_launch(void* const* d_in, const int* in_sizes, int n_in,
                              void* d_out, int out_size) {
    const float* hs = (const float*)d_in[0];
    const float* Wq = (const float*)d_in[1];
    const float* bq = (const float*)d_in[2];
    const float* Wk = (const float*)d_in[3];
    const float* bk = (const float*)d_in[4];
    const float* Wv = (const float*)d_in[5];
    const float* bv = (const float*)d_in[6];
    const float* Wo = (const float*)d_in[7];
    const float* bo = (const float*)d_in[8];
    float* out = (float*)d_out;

    static bool attr_set = false;
    if (!attr_set) {
        cudaFuncSetAttribute(k_hgemm, cudaFuncAttributeMaxDynamicSharedMemorySize, GEMM_SMEM);
        cudaFuncSetAttribute(k_fattn, cudaFuncAttributeMaxDynamicSharedMemorySize, FA_SMEM);
        attr_set = true;
    }

    __half* w16;
    cudaGetSymbolAddress((void**)&w16, g_w16);
    __half* hs16;
    cudaGetSymbolAddress((void**)&hs16, g_hs16);

    k_tohalf<<<(NTOK * (long)Dd) / 2048, 256>>>(hs, hs16);
    k_tohalf<<<((long)Dd * Dd) / 2048, 256>>>(Wq, w16);
    k_tohalf<<<((long)Dd * Dd) / 2048, 256>>>(Wk, w16 + (long)Dd * Dd);
    k_tohalf<<<((long)Dd * Dd) / 2048, 256>>>(Wv, w16 + (long)2 * Dd * Dd);
    k_tohalf<<<((long)Dd * Dd) / 2048, 256>>>(Wo, w16 + (long)3 * Dd * Dd);

    // QKV projections (+bias, +RoPE q/k, transpose v)
    k_hgemm<<<dim3(Dd / 128, NTOK / 128, 3), 256, GEMM_SMEM>>>(bq, bk, bv, nullptr, 0);
    // fused flash attention -> ctx fp16
    k_fattn<<<dim3(Sd / 128, BH), 256, FA_SMEM>>>();
    // out = ctx Wo^T + bo
    k_hgemm<<<dim3(Dd / 128, NTOK / 128, 1), 256, GEMM_SMEM>>>(bo, nullptr, nullptr, out, 5);
}